// round 14
// baseline (speedup 1.0000x reference)
#include <cuda_runtime.h>
#include <cuda_bf16.h>
#include <cstdint>

#define NW   960
#define NT   144
#define DIMM 192
#define NH   6
#define HD   32
#define NQKV 576
#define MROWS (NW*NT)
#define QSCALE 0.17677669529663689f
#define BIAS_ELEMS (NH*NT*NT)
#define MT16  (MROWS/16)
#define KSTEPS 12
#define A_PK  (MT16*KSTEPS*128)
#define HPK   (NW*NH*2304)

__device__ float g_ctx[MROWS*DIMM];
__device__ float g_bias[BIAS_ELEMS];
__device__ float g_vT[NW*NH*HD*NT];
__device__ uint32_t g_mbits[NW*NT*5];         // mask bit-packed: 144 bits/row
__device__ uint32_t g_qpk_hi[HPK], g_qpk_lo[HPK];
__device__ uint32_t g_kpk_hi[HPK], g_kpk_lo[HPK];
__device__ uint32_t g_xpk_hi[A_PK], g_xpk_lo[A_PK];
__device__ uint32_t g_cpk_hi[A_PK], g_cpk_lo[A_PK];
__device__ uint32_t g_wq_hi[9*12*512],  g_wq_lo[9*12*512];
__device__ uint32_t g_wo_hi[3*12*512],  g_wo_lo[3*12*512];

__device__ __forceinline__ uint32_t bfpack(float a, float b) {
    __nv_bfloat162 t = __floats2bfloat162_rn(a, b);
    return *reinterpret_cast<uint32_t*>(&t);
}
__device__ __forceinline__ void split2(float a, float b, uint32_t& hi, uint32_t& lo) {
    hi = bfpack(a, b);
    __nv_bfloat162 h = *reinterpret_cast<__nv_bfloat162*>(&hi);
    lo = bfpack(a - __bfloat162float(h.x), b - __bfloat162float(h.y));
}
__device__ __forceinline__ void mma_bf16(float* d, const uint32_t* a, const uint32_t* b) {
    asm volatile("mma.sync.aligned.m16n8k16.row.col.f32.bf16.bf16.f32 "
        "{%0,%1,%2,%3}, {%4,%5,%6,%7}, {%8,%9}, {%0,%1,%2,%3};"
        : "+f"(d[0]), "+f"(d[1]), "+f"(d[2]), "+f"(d[3])
        : "r"(a[0]), "r"(a[1]), "r"(a[2]), "r"(a[3]), "r"(b[0]), "r"(b[1]));
}

__device__ __forceinline__ int apk_idx(int m, int k) {
    int mtile = m >> 4, mr = m & 15, kstep = k >> 4, kk = k & 15;
    int lane = (mr & 7) * 4 + ((kk & 7) >> 1);
    int reg  = ((mr >> 3) & 1) + ((kk >> 3) << 1);
    return ((mtile * KSTEPS + kstep) * 32 + lane) * 4 + reg;
}
__device__ __forceinline__ int bpk_idx(int n, int k) {
    int block = n >> 6, nl = n & 63, ntile = nl >> 3, g = nl & 7;
    int kstep = k >> 4, kk = k & 15;
    int lane = g * 4 + ((kk & 7) >> 1);
    int reg  = (kk >> 3) & 1;
    return ((block * KSTEPS + kstep) * 8 + ntile) * 64 + lane * 2 + reg;
}

// ---------------- prep: bias expand + weight packs ----------------
__global__ void prep_kernel(const int* __restrict__ rel, const float* __restrict__ table,
                            const float* __restrict__ w_qkv, const float* __restrict__ w_out) {
    int id = blockIdx.x * 256 + threadIdx.x;
    if (id < BIAS_ELEMS) {
        int h = id / (NT * NT), nm = id - h * (NT * NT);
        g_bias[id] = table[rel[nm] * NH + h];
    }
    if (id < NQKV * 96) {
        int n = id / 96, k = (id % 96) * 2;
        split2(w_qkv[k * NQKV + n], w_qkv[(k + 1) * NQKV + n],
               g_wq_hi[bpk_idx(n, k)], g_wq_lo[bpk_idx(n, k)]);
    }
    if (id < DIMM * 96) {
        int n = id / 96, k = (id % 96) * 2;
        split2(w_out[k * DIMM + n], w_out[(k + 1) * DIMM + n],
               g_wo_hi[bpk_idx(n, k)], g_wo_lo[bpk_idx(n, k)]);
    }
}

// ---------------- mask bit-pack: one word per (w,n,j) ----------------
__global__ void maskbits_kernel(const int* __restrict__ mask) {
    int id = blockIdx.x * 256 + threadIdx.x;     // over NW*NT*5
    if (id >= NW * NT * 5) return;
    int j = id % 5, row = id / 5;                // row = w*NT + n
    int m0 = j * 32;
    const int* mr = mask + (size_t)row * NT;     // [w][n][*] is contiguous
    uint32_t bits = 0;
    int lim = NT - m0; if (lim > 32) lim = 32;
    for (int b = 0; b < lim; b++)
        bits |= (mr[m0 + b] != 0 ? 1u : 0u) << b;
    g_mbits[id] = bits;
}

// ---------------- pack activations ----------------
template <int SRC>
__global__ void pack_a_kernel(const float* __restrict__ x) {
    int id = blockIdx.x * 256 + threadIdx.x;
    int m = id / 96, k = (id % 96) * 2;
    const float* src = (SRC == 0) ? x : g_ctx;
    float2 v = *(const float2*)&src[(size_t)m * DIMM + k];
    int idx = apk_idx(m, k);
    if (SRC == 0) split2(v.x, v.y, g_xpk_hi[idx], g_xpk_lo[idx]);
    else          split2(v.x, v.y, g_cpk_hi[idx], g_cpk_lo[idx]);
}

// ---------------- bf16-split tensor GEMM (R13-verified) ----------------
template <int EPI>
__global__ __launch_bounds__(256)
void gemm_mma(const float* __restrict__ bias, float* __restrict__ C) {
    extern __shared__ uint4 smem4[];
    uint4* Asm = smem4;
    uint4* Bsm = smem4 + 2048;

    const int tid = threadIdx.x, lane = tid & 31, wid = tid >> 5;
    const int wm = wid >> 1, wn = wid & 1;
    const int m0t = blockIdx.y * 8;
    const int block = blockIdx.x;

    const uint4* Ahi = (const uint4*)((EPI == 0) ? g_xpk_hi : g_cpk_hi);
    const uint4* Alo = (const uint4*)((EPI == 0) ? g_xpk_lo : g_cpk_lo);
    const uint4* Bhi = (const uint4*)((EPI == 0) ? g_wq_hi  : g_wo_hi);
    const uint4* Blo = (const uint4*)((EPI == 0) ? g_wq_lo  : g_wo_lo);

    float acc[2][4][4];
#pragma unroll
    for (int mt = 0; mt < 2; mt++)
#pragma unroll
        for (int nt = 0; nt < 4; nt++)
#pragma unroll
            for (int r = 0; r < 4; r++) acc[mt][nt][r] = 0.f;

    auto a_gidx = [&](int u, int c) {
        int mt = (u & 511) >> 6, j = (u >> 5) & 1, q = u & 31;
        return ((m0t + mt) * KSTEPS + 2 * c + j) * 32 + q;
    };
    auto b_gidx = [&](int u, int c) {
        int j = (u >> 7) & 1, nt = (u >> 4) & 7, q = u & 15;
        return ((block * KSTEPS + 2 * c + j) * 8 + nt) * 16 + q;
    };

#pragma unroll
    for (int i = 0; i < 4; i++) {
        int u = tid + 256 * i;
        Asm[u] = (u < 512 ? Ahi : Alo)[a_gidx(u, 0)];
    }
#pragma unroll
    for (int i = 0; i < 2; i++) {
        int u = tid + 256 * i;
        Bsm[u] = (u < 256 ? Bhi : Blo)[b_gidx(u, 0)];
    }
    __syncthreads();

    uint4 pa[4], pb[2];
#pragma unroll 1
    for (int c = 0; c < 6; c++) {
        const int s = c & 1;
        if (c < 5) {
#pragma unroll
            for (int i = 0; i < 4; i++) {
                int u = tid + 256 * i;
                pa[i] = (u < 512 ? Ahi : Alo)[a_gidx(u, c + 1)];
            }
#pragma unroll
            for (int i = 0; i < 2; i++) {
                int u = tid + 256 * i;
                pb[i] = (u < 256 ? Bhi : Blo)[b_gidx(u, c + 1)];
            }
        }
        const uint4* As = Asm + s * 1024;
        const uint2* Bs2 = (const uint2*)(Bsm + s * 512);
#pragma unroll
        for (int j = 0; j < 2; j++) {
            uint4 ah[2], al[2];
#pragma unroll
            for (int mt = 0; mt < 2; mt++) {
                ah[mt] = As[(wm * 2 + mt) * 64 + j * 32 + lane];
                al[mt] = As[512 + (wm * 2 + mt) * 64 + j * 32 + lane];
            }
            uint2 bh[4], bl[4];
#pragma unroll
            for (int nt = 0; nt < 4; nt++) {
                bh[nt] = Bs2[(j * 8 + wn * 4 + nt) * 32 + lane];
                bl[nt] = Bs2[512 + (j * 8 + wn * 4 + nt) * 32 + lane];
            }
#pragma unroll
            for (int mt = 0; mt < 2; mt++)
#pragma unroll
                for (int nt = 0; nt < 4; nt++) {
                    mma_bf16(acc[mt][nt], (const uint32_t*)&ah[mt], (const uint32_t*)&bh[nt]);
                    mma_bf16(acc[mt][nt], (const uint32_t*)&ah[mt], (const uint32_t*)&bl[nt]);
                    mma_bf16(acc[mt][nt], (const uint32_t*)&al[mt], (const uint32_t*)&bh[nt]);
                }
        }
        if (c < 5) {
            uint4* Ad = Asm + (s ^ 1) * 1024;
            uint4* Bd = Bsm + (s ^ 1) * 512;
#pragma unroll
            for (int i = 0; i < 4; i++) Ad[tid + 256 * i] = pa[i];
#pragma unroll
            for (int i = 0; i < 2; i++) Bd[tid + 256 * i] = pb[i];
        }
        __syncthreads();
    }

    const int g = lane >> 2, t = lane & 3;
#pragma unroll
    for (int mt = 0; mt < 2; mt++) {
        const int r0 = m0t * 16 + wm * 32 + mt * 16 + g;
#pragma unroll
        for (int nt = 0; nt < 4; nt++) {
            const int cn = wn * 32 + nt * 8 + 2 * t;
            const float2 bi = *(const float2*)&bias[block * 64 + cn];
            float2 v0 = make_float2(acc[mt][nt][0] + bi.x, acc[mt][nt][1] + bi.y);
            float2 v1 = make_float2(acc[mt][nt][2] + bi.x, acc[mt][nt][3] + bi.y);
            if (EPI == 0) {
                const int comp = block / 3;
                const int n = (block % 3) * 64 + cn;
                const int h = n >> 5, d = n & 31;
                const int ks = d >> 4, kk = d & 15;
                const int w0 = r0 / NT, tok0 = r0 - w0 * NT;
                const int tok1 = tok0 + 8;
                const size_t hb = (size_t)(w0 * NH + h);
                if (comp == 0) {
                    v0.x *= QSCALE; v0.y *= QSCALE; v1.x *= QSCALE; v1.y *= QSCALE;
                    const int mt9 = tok0 >> 4;
                    const int ln = ((tok0 & 7) * 4) + ((kk & 7) >> 1);
                    const int rbase = ((kk >> 3) & 1) << 1;
                    const size_t ib = ((hb * 9 + mt9) * 2 + ks) * 128 + ln * 4;
                    uint32_t hi0, lo0, hi1, lo1;
                    split2(v0.x, v0.y, hi0, lo0);
                    split2(v1.x, v1.y, hi1, lo1);
                    g_qpk_hi[ib + rbase]     = hi0; g_qpk_lo[ib + rbase]     = lo0;
                    g_qpk_hi[ib + rbase + 1] = hi1; g_qpk_lo[ib + rbase + 1] = lo1;
                } else if (comp == 1) {
                    const int rg = (kk >> 3) & 1;
                    const int lk = (kk & 7) >> 1;
                    const size_t kb = hb * 2304;
                    {
                        const int ntk = tok0 >> 3, ln = (tok0 & 7) * 4 + lk;
                        uint32_t hi, lo; split2(v0.x, v0.y, hi, lo);
                        const size_t ix = kb + (ntk * 2 + ks) * 64 + ln * 2 + rg;
                        g_kpk_hi[ix] = hi; g_kpk_lo[ix] = lo;
                    }
                    {
                        const int ntk = tok1 >> 3, ln = (tok1 & 7) * 4 + lk;
                        uint32_t hi, lo; split2(v1.x, v1.y, hi, lo);
                        const size_t ix = kb + (ntk * 2 + ks) * 64 + ln * 2 + rg;
                        g_kpk_hi[ix] = hi; g_kpk_lo[ix] = lo;
                    }
                } else {
                    float* vt = g_vT + hb * HD * NT;
                    vt[d * NT + tok0]       = v0.x;
                    vt[(d + 1) * NT + tok0] = v0.y;
                    vt[d * NT + tok1]       = v1.x;
                    vt[(d + 1) * NT + tok1] = v1.y;
                }
            } else {
                *(float2*)&C[(size_t)r0 * DIMM + block * 64 + cn] = v0;
                *(float2*)&C[(size_t)(r0 + 8) * DIMM + block * 64 + cn] = v1;
            }
        }
    }
}

// ---------------- attention: one CTA per (w,h); mask via L2-resident bitwords ----------------
__global__ __launch_bounds__(288, 2)
void attn_kernel() {
    __shared__ uint32_t v_hi[2304], v_lo[2304];

    const int wh = blockIdx.x;
    const int h = wh % NH, w = wh / NH;
    const int tid = threadIdx.x, lane = tid & 31, wm = tid >> 5;
    const size_t hb = (size_t)(w * NH + h);

    // ---- v conversion (contiguous float2 from vT) ----
    const float* vt = g_vT + hb * HD * NT;
#pragma unroll
    for (int it = 0; it < 8; it++) {
        int p = tid + 288 * it;
        int rest = p >> 6, ln = (p >> 1) & 31, rg = p & 1;
        int nt = rest / 9, kt = rest - nt * 9;
        int d = nt * 8 + (ln >> 2);
        int tok = kt * 16 + 2 * (ln & 3) + 8 * rg;
        float2 vv = *(const float2*)&vt[d * NT + tok];
        split2(vv.x, vv.y, v_hi[p], v_lo[p]);
    }

    // ---- QK^T ----
    float acc[18][4];
#pragma unroll
    for (int nt = 0; nt < 18; nt++)
#pragma unroll
        for (int r = 0; r < 4; r++) acc[nt][r] = 0.f;

    const uint32_t* qh = g_qpk_hi + (hb * 9 + wm) * 256;
    const uint32_t* ql = g_qpk_lo + (hb * 9 + wm) * 256;
    uint4 qa_h[2], qa_l[2];
#pragma unroll
    for (int ks = 0; ks < 2; ks++) {
        qa_h[ks] = *(const uint4*)&qh[ks * 128 + lane * 4];
        qa_l[ks] = *(const uint4*)&ql[ks * 128 + lane * 4];
    }
    const uint32_t* kh = g_kpk_hi + hb * 2304;
    const uint32_t* kl = g_kpk_lo + hb * 2304;
#pragma unroll
    for (int ks = 0; ks < 2; ks++) {
#pragma unroll
        for (int nt = 0; nt < 18; nt++) {
            uint2 bh = *(const uint2*)&kh[(nt * 2 + ks) * 64 + lane * 2];
            uint2 bl = *(const uint2*)&kl[(nt * 2 + ks) * 64 + lane * 2];
            mma_bf16(acc[nt], (const uint32_t*)&qa_h[ks], (const uint32_t*)&bh);
            mma_bf16(acc[nt], (const uint32_t*)&qa_h[ks], (const uint32_t*)&bl);
            mma_bf16(acc[nt], (const uint32_t*)&qa_l[ks], (const uint32_t*)&bh);
        }
    }

    // ---- bias (L2) + mask bits (L2) + softmax in accumulator layout ----
    const int g = lane >> 2, t = lane & 3;
    const int rA = wm * 16 + g, rB = rA + 8;
    {
        uint32_t wA[5], wB[5];
        const uint32_t* mba = g_mbits + (size_t)(w * NT + rA) * 5;
        const uint32_t* mbb = g_mbits + (size_t)(w * NT + rB) * 5;
#pragma unroll
        for (int j = 0; j < 5; j++) { wA[j] = mba[j]; wB[j] = mbb[j]; }

        const float* bb = g_bias + h * NT * NT;
#pragma unroll
        for (int nt = 0; nt < 18; nt++) {
            const int cn = nt * 8 + 2 * t;
            float2 bA = *(const float2*)&bb[rA * NT + cn];
            float2 bB = *(const float2*)&bb[rB * NT + cn];
            const uint32_t bitsA = wA[cn >> 5] >> (cn & 31);
            const uint32_t bitsB = wB[cn >> 5] >> (cn & 31);
            acc[nt][0] = (bitsA & 1u) ? acc[nt][0] + bA.x : -1.0e9f;
            acc[nt][1] = (bitsA & 2u) ? acc[nt][1] + bA.y : -1.0e9f;
            acc[nt][2] = (bitsB & 1u) ? acc[nt][2] + bB.x : -1.0e9f;
            acc[nt][3] = (bitsB & 2u) ? acc[nt][3] + bB.y : -1.0e9f;
        }
        float mxA = -3.0e38f, mxB = -3.0e38f;
#pragma unroll
        for (int nt = 0; nt < 18; nt++) {
            mxA = fmaxf(mxA, fmaxf(acc[nt][0], acc[nt][1]));
            mxB = fmaxf(mxB, fmaxf(acc[nt][2], acc[nt][3]));
        }
#pragma unroll
        for (int o = 1; o <= 2; o <<= 1) {
            mxA = fmaxf(mxA, __shfl_xor_sync(0xffffffffu, mxA, o));
            mxB = fmaxf(mxB, __shfl_xor_sync(0xffffffffu, mxB, o));
        }
        float sA = 0.f, sB = 0.f;
#pragma unroll
        for (int nt = 0; nt < 18; nt++) {
            acc[nt][0] = __expf(acc[nt][0] - mxA); sA += acc[nt][0];
            acc[nt][1] = __expf(acc[nt][1] - mxA); sA += acc[nt][1];
            acc[nt][2] = __expf(acc[nt][2] - mxB); sB += acc[nt][2];
            acc[nt][3] = __expf(acc[nt][3] - mxB); sB += acc[nt][3];
        }
#pragma unroll
        for (int o = 1; o <= 2; o <<= 1) {
            sA += __shfl_xor_sync(0xffffffffu, sA, o);
            sB += __shfl_xor_sync(0xffffffffu, sB, o);
        }
        const float iA = 1.f / sA, iB = 1.f / sB;
#pragma unroll
        for (int nt = 0; nt < 18; nt++) {
            acc[nt][0] *= iA; acc[nt][1] *= iA;
            acc[nt][2] *= iB; acc[nt][3] *= iB;
        }
    }

    __syncthreads();

    // ---- PV ----
    float o4[4][4];
#pragma unroll
    for (int nt = 0; nt < 4; nt++)
#pragma unroll
        for (int r = 0; r < 4; r++) o4[nt][r] = 0.f;

#pragma unroll
    for (int kt = 0; kt < 9; kt++) {
        uint32_t ah[4], al[4];
        split2(acc[2 * kt][0],     acc[2 * kt][1],     ah[0], al[0]);
        split2(acc[2 * kt][2],     acc[2 * kt][3],     ah[1], al[1]);
        split2(acc[2 * kt + 1][0], acc[2 * kt + 1][1], ah[2], al[2]);
        split2(acc[2 * kt + 1][2], acc[2 * kt + 1][3], ah[3], al[3]);
#pragma unroll
        for (int nt = 0; nt < 4; nt++) {
            uint2 bh = *(const uint2*)&v_hi[((nt * 9 + kt) * 32 + lane) * 2];
            uint2 bl = *(const uint2*)&v_lo[((nt * 9 + kt) * 32 + lane) * 2];
            mma_bf16(o4[nt], ah, (const uint32_t*)&bh);
            mma_bf16(o4[nt], ah, (const uint32_t*)&bl);
            mma_bf16(o4[nt], al, (const uint32_t*)&bh);
        }
    }

#pragma unroll
    for (int nt = 0; nt < 4; nt++) {
        const int cn = h * HD + nt * 8 + 2 * t;
        *(float2*)&g_ctx[(w * NT + rA) * DIMM + cn] = make_float2(o4[nt][0], o4[nt][1]);
        *(float2*)&g_ctx[(w * NT + rB) * DIMM + cn] = make_float2(o4[nt][2], o4[nt][3]);
    }
}

// ---------------- launch ----------------
extern "C" void kernel_launch(void* const* d_in, const int* in_sizes, int n_in,
                              void* d_out, int out_size) {
    const float* x     = (const float*)d_in[0];
    const int*   mask  = (const int*)  d_in[1];
    const int*   rel   = (const int*)  d_in[2];
    const float* w_qkv = (const float*)d_in[3];
    const float* b_qkv = (const float*)d_in[4];
    const float* w_out = (const float*)d_in[5];
    const float* b_out = (const float*)d_in[6];
    const float* btab  = (const float*)d_in[7];
    float*       out   = (float*)d_out;

    cudaStream_t stream = cudaStreamLegacy;
    cudaStreamCaptureStatus st = cudaStreamCaptureStatusNone;
    if (cudaStreamIsCapturing(cudaStreamPerThread, &st) == cudaSuccess &&
        st == cudaStreamCaptureStatusActive) {
        stream = cudaStreamPerThread;
    }

    const int GEMM_SMEM = 49152;
    cudaFuncSetAttribute(gemm_mma<0>,
                         cudaFuncAttributeMaxDynamicSharedMemorySize, GEMM_SMEM);
    cudaFuncSetAttribute(gemm_mma<1>,
                         cudaFuncAttributeMaxDynamicSharedMemorySize, GEMM_SMEM);

    prep_kernel<<<(BIAS_ELEMS + 255) / 256, 256, 0, stream>>>(rel, btab, w_qkv, w_out);
    maskbits_kernel<<<(NW * NT * 5 + 255) / 256, 256, 0, stream>>>(mask);
    pack_a_kernel<0><<<A_PK / 256, 256, 0, stream>>>(x);

    {
        dim3 grid(9, MROWS / 128);
        gemm_mma<0><<<grid, 256, GEMM_SMEM, stream>>>(b_qkv, nullptr);
    }

    attn_kernel<<<NW * NH, 288, 0, stream>>>();

    pack_a_kernel<1><<<A_PK / 256, 256, 0, stream>>>(nullptr);
    {
        dim3 grid(3, MROWS / 128);
        gemm_mma<1><<<grid, 256, GEMM_SMEM, stream>>>(b_out, out);
    }
}

// round 15
// speedup vs baseline: 1.1662x; 1.1662x over previous
#include <cuda_runtime.h>
#include <cuda_bf16.h>
#include <cstdint>

#define NW   960
#define NT   144
#define DIMM 192
#define NH   6
#define HD   32
#define NQKV 576
#define MROWS (NW*NT)
#define QSCALE 0.17677669529663689f
#define BIAS_ELEMS (NH*NT*NT)
#define MT16  (MROWS/16)
#define KSTEPS 12
#define A_PK  (MT16*KSTEPS*128)
#define HPK   (NW*NH*2304)

__device__ float g_bias[BIAS_ELEMS];
__device__ float g_vT[NW*NH*HD*NT];
__device__ uint32_t g_mbits[NW*NT*5];
__device__ uint32_t g_qpk_hi[HPK], g_qpk_lo[HPK];
__device__ uint32_t g_kpk_hi[HPK], g_kpk_lo[HPK];
__device__ uint32_t g_xpk_hi[A_PK], g_xpk_lo[A_PK];
__device__ uint32_t g_cpk_hi[A_PK], g_cpk_lo[A_PK];
__device__ uint32_t g_wq_hi[9*12*512],  g_wq_lo[9*12*512];
__device__ uint32_t g_wo_hi[3*12*512],  g_wo_lo[3*12*512];

__device__ __forceinline__ uint32_t bfpack(float a, float b) {
    __nv_bfloat162 t = __floats2bfloat162_rn(a, b);
    return *reinterpret_cast<uint32_t*>(&t);
}
__device__ __forceinline__ void split2(float a, float b, uint32_t& hi, uint32_t& lo) {
    hi = bfpack(a, b);
    __nv_bfloat162 h = *reinterpret_cast<__nv_bfloat162*>(&hi);
    lo = bfpack(a - __bfloat162float(h.x), b - __bfloat162float(h.y));
}
__device__ __forceinline__ void mma_bf16(float* d, const uint32_t* a, const uint32_t* b) {
    asm volatile("mma.sync.aligned.m16n8k16.row.col.f32.bf16.bf16.f32 "
        "{%0,%1,%2,%3}, {%4,%5,%6,%7}, {%8,%9}, {%0,%1,%2,%3};"
        : "+f"(d[0]), "+f"(d[1]), "+f"(d[2]), "+f"(d[3])
        : "r"(a[0]), "r"(a[1]), "r"(a[2]), "r"(a[3]), "r"(b[0]), "r"(b[1]));
}
__device__ __forceinline__ uint32_t smem_u32(const void* p) {
    uint32_t a;
    asm("{ .reg .u64 t; cvta.to.shared.u64 t, %1; cvt.u32.u64 %0, t; }" : "=r"(a) : "l"(p));
    return a;
}
#define CP_ASYNC16(dst, src) \
    asm volatile("cp.async.cg.shared.global [%0], [%1], 16;" :: "r"(dst), "l"(src))
#define CP_COMMIT() asm volatile("cp.async.commit_group;")
#define CP_WAIT0()  asm volatile("cp.async.wait_group 0;")

__device__ __forceinline__ int apk_idx(int m, int k) {
    int mtile = m >> 4, mr = m & 15, kstep = k >> 4, kk = k & 15;
    int lane = (mr & 7) * 4 + ((kk & 7) >> 1);
    int reg  = ((mr >> 3) & 1) + ((kk >> 3) << 1);
    return ((mtile * KSTEPS + kstep) * 32 + lane) * 4 + reg;
}
__device__ __forceinline__ int bpk_idx(int n, int k) {
    int block = n >> 6, nl = n & 63, ntile = nl >> 3, g = nl & 7;
    int kstep = k >> 4, kk = k & 15;
    int lane = g * 4 + ((kk & 7) >> 1);
    int reg  = (kk >> 3) & 1;
    return ((block * KSTEPS + kstep) * 8 + ntile) * 64 + lane * 2 + reg;
}

// ---------------- prep: bias expand + weight packs ----------------
__global__ void prep_kernel(const int* __restrict__ rel, const float* __restrict__ table,
                            const float* __restrict__ w_qkv, const float* __restrict__ w_out) {
    int id = blockIdx.x * 256 + threadIdx.x;
    if (id < BIAS_ELEMS) {
        int h = id / (NT * NT), nm = id - h * (NT * NT);
        g_bias[id] = table[rel[nm] * NH + h];
    }
    if (id < NQKV * 96) {
        int n = id / 96, k = (id % 96) * 2;
        split2(w_qkv[k * NQKV + n], w_qkv[(k + 1) * NQKV + n],
               g_wq_hi[bpk_idx(n, k)], g_wq_lo[bpk_idx(n, k)]);
    }
    if (id < DIMM * 96) {
        int n = id / 96, k = (id % 96) * 2;
        split2(w_out[k * DIMM + n], w_out[(k + 1) * DIMM + n],
               g_wo_hi[bpk_idx(n, k)], g_wo_lo[bpk_idx(n, k)]);
    }
}

// ---------------- mask bit-pack ----------------
__global__ void maskbits_kernel(const int* __restrict__ mask) {
    int id = blockIdx.x * 256 + threadIdx.x;
    if (id >= NW * NT * 5) return;
    int j = id % 5, row = id / 5;
    int m0 = j * 32;
    const int* mr = mask + (size_t)row * NT;
    uint32_t bits = 0;
    int lim = NT - m0; if (lim > 32) lim = 32;
    for (int b = 0; b < lim; b++)
        bits |= (mr[m0 + b] != 0 ? 1u : 0u) << b;
    g_mbits[id] = bits;
}

// ---------------- pack x ----------------
__global__ void pack_a_kernel(const float* __restrict__ x) {
    int id = blockIdx.x * 256 + threadIdx.x;
    int m = id / 96, k = (id % 96) * 2;
    float2 v = *(const float2*)&x[(size_t)m * DIMM + k];
    int idx = apk_idx(m, k);
    split2(v.x, v.y, g_xpk_hi[idx], g_xpk_lo[idx]);
}

// ---------------- bf16-split tensor GEMM, cp.async double-buffered ----------------
template <int EPI>
__global__ __launch_bounds__(256, 3)
void gemm_mma(const float* __restrict__ bias, float* __restrict__ C) {
    extern __shared__ uint4 smem4[];
    uint4* Asm = smem4;            // [2][1024]
    uint4* Bsm = smem4 + 2048;     // [2][512]
    const uint32_t sb = smem_u32(smem4);

    const int tid = threadIdx.x, lane = tid & 31, wid = tid >> 5;
    const int wm = wid >> 1, wn = wid & 1;
    const int m0t = blockIdx.y * 8;
    const int block = blockIdx.x;

    const uint4* Ahi = (const uint4*)((EPI == 0) ? g_xpk_hi : g_cpk_hi);
    const uint4* Alo = (const uint4*)((EPI == 0) ? g_xpk_lo : g_cpk_lo);
    const uint4* Bhi = (const uint4*)((EPI == 0) ? g_wq_hi  : g_wo_hi);
    const uint4* Blo = (const uint4*)((EPI == 0) ? g_wq_lo  : g_wo_lo);

    float acc[2][4][4];
#pragma unroll
    for (int mt = 0; mt < 2; mt++)
#pragma unroll
        for (int nt = 0; nt < 4; nt++)
#pragma unroll
            for (int r = 0; r < 4; r++) acc[mt][nt][r] = 0.f;

    auto a_gidx = [&](int u, int c) {
        int mt = (u & 511) >> 6, j = (u >> 5) & 1, q = u & 31;
        return ((m0t + mt) * KSTEPS + 2 * c + j) * 32 + q;
    };
    auto b_gidx = [&](int u, int c) {
        int j = (u >> 7) & 1, nt = (u >> 4) & 7, q = u & 15;
        return ((block * KSTEPS + 2 * c + j) * 8 + nt) * 16 + q;
    };
    auto issue_stage = [&](int c, int s) {
        const uint32_t da = sb + s * 16384;
#pragma unroll
        for (int i = 0; i < 4; i++) {
            int u = tid + 256 * i;
            const uint4* src = (u < 512 ? Ahi : Alo) + a_gidx(u, c);
            CP_ASYNC16(da + u * 16, src);
        }
        const uint32_t db = sb + 32768 + s * 8192;
#pragma unroll
        for (int i = 0; i < 2; i++) {
            int u = tid + 256 * i;
            const uint4* src = (u < 256 ? Bhi : Blo) + b_gidx(u, c);
            CP_ASYNC16(db + u * 16, src);
        }
        CP_COMMIT();
    };

    issue_stage(0, 0);
    CP_WAIT0();
    __syncthreads();

#pragma unroll 1
    for (int c = 0; c < 6; c++) {
        const int s = c & 1;
        if (c < 5) issue_stage(c + 1, s ^ 1);   // overlaps with compute below
        const uint4* As = Asm + s * 1024;
        const uint2* Bs2 = (const uint2*)(Bsm + s * 512);
#pragma unroll
        for (int j = 0; j < 2; j++) {
            uint4 ah[2], al[2];
#pragma unroll
            for (int mt = 0; mt < 2; mt++) {
                ah[mt] = As[(wm * 2 + mt) * 64 + j * 32 + lane];
                al[mt] = As[512 + (wm * 2 + mt) * 64 + j * 32 + lane];
            }
            uint2 bh[4], bl[4];
#pragma unroll
            for (int nt = 0; nt < 4; nt++) {
                bh[nt] = Bs2[(j * 8 + wn * 4 + nt) * 32 + lane];
                bl[nt] = Bs2[512 + (j * 8 + wn * 4 + nt) * 32 + lane];
            }
#pragma unroll
            for (int mt = 0; mt < 2; mt++)
#pragma unroll
                for (int nt = 0; nt < 4; nt++) {
                    mma_bf16(acc[mt][nt], (const uint32_t*)&ah[mt], (const uint32_t*)&bh[nt]);
                    mma_bf16(acc[mt][nt], (const uint32_t*)&ah[mt], (const uint32_t*)&bl[nt]);
                    mma_bf16(acc[mt][nt], (const uint32_t*)&al[mt], (const uint32_t*)&bh[nt]);
                }
        }
        if (c < 5) {
            CP_WAIT0();
            __syncthreads();
        }
    }

    const int g = lane >> 2, t = lane & 3;
#pragma unroll
    for (int mt = 0; mt < 2; mt++) {
        const int r0 = m0t * 16 + wm * 32 + mt * 16 + g;
#pragma unroll
        for (int nt = 0; nt < 4; nt++) {
            const int cn = wn * 32 + nt * 8 + 2 * t;
            const float2 bi = *(const float2*)&bias[block * 64 + cn];
            float2 v0 = make_float2(acc[mt][nt][0] + bi.x, acc[mt][nt][1] + bi.y);
            float2 v1 = make_float2(acc[mt][nt][2] + bi.x, acc[mt][nt][3] + bi.y);
            if (EPI == 0) {
                const int comp = block / 3;
                const int n = (block % 3) * 64 + cn;
                const int h = n >> 5, d = n & 31;
                const int ks = d >> 4, kk = d & 15;
                const int w0 = r0 / NT, tok0 = r0 - w0 * NT;
                const int tok1 = tok0 + 8;
                const size_t hb = (size_t)(w0 * NH + h);
                if (comp == 0) {
                    v0.x *= QSCALE; v0.y *= QSCALE; v1.x *= QSCALE; v1.y *= QSCALE;
                    const int mt9 = tok0 >> 4;
                    const int ln = ((tok0 & 7) * 4) + ((kk & 7) >> 1);
                    const int rbase = ((kk >> 3) & 1) << 1;
                    const size_t ib = ((hb * 9 + mt9) * 2 + ks) * 128 + ln * 4;
                    uint32_t hi0, lo0, hi1, lo1;
                    split2(v0.x, v0.y, hi0, lo0);
                    split2(v1.x, v1.y, hi1, lo1);
                    g_qpk_hi[ib + rbase]     = hi0; g_qpk_lo[ib + rbase]     = lo0;
                    g_qpk_hi[ib + rbase + 1] = hi1; g_qpk_lo[ib + rbase + 1] = lo1;
                } else if (comp == 1) {
                    const int rg = (kk >> 3) & 1;
                    const int lk = (kk & 7) >> 1;
                    const size_t kb = hb * 2304;
                    {
                        const int ntk = tok0 >> 3, ln = (tok0 & 7) * 4 + lk;
                        uint32_t hi, lo; split2(v0.x, v0.y, hi, lo);
                        const size_t ix = kb + (ntk * 2 + ks) * 64 + ln * 2 + rg;
                        g_kpk_hi[ix] = hi; g_kpk_lo[ix] = lo;
                    }
                    {
                        const int ntk = tok1 >> 3, ln = (tok1 & 7) * 4 + lk;
                        uint32_t hi, lo; split2(v1.x, v1.y, hi, lo);
                        const size_t ix = kb + (ntk * 2 + ks) * 64 + ln * 2 + rg;
                        g_kpk_hi[ix] = hi; g_kpk_lo[ix] = lo;
                    }
                } else {
                    float* vt = g_vT + hb * HD * NT;
                    vt[d * NT + tok0]       = v0.x;
                    vt[(d + 1) * NT + tok0] = v0.y;
                    vt[d * NT + tok1]       = v1.x;
                    vt[(d + 1) * NT + tok1] = v1.y;
                }
            } else {
                *(float2*)&C[(size_t)r0 * DIMM + block * 64 + cn] = v0;
                *(float2*)&C[(size_t)(r0 + 8) * DIMM + block * 64 + cn] = v1;
            }
        }
    }
}

// ---------------- attention: epilogue writes cpk fragments directly ----------------
__global__ __launch_bounds__(288, 2)
void attn_kernel() {
    __shared__ uint32_t v_hi[2304], v_lo[2304];

    const int wh = blockIdx.x;
    const int h = wh % NH, w = wh / NH;
    const int tid = threadIdx.x, lane = tid & 31, wm = tid >> 5;
    const size_t hb = (size_t)(w * NH + h);

    const float* vt = g_vT + hb * HD * NT;
#pragma unroll
    for (int it = 0; it < 8; it++) {
        int p = tid + 288 * it;
        int rest = p >> 6, ln = (p >> 1) & 31, rg = p & 1;
        int nt = rest / 9, kt = rest - nt * 9;
        int d = nt * 8 + (ln >> 2);
        int tok = kt * 16 + 2 * (ln & 3) + 8 * rg;
        float2 vv = *(const float2*)&vt[d * NT + tok];
        split2(vv.x, vv.y, v_hi[p], v_lo[p]);
    }

    float acc[18][4];
#pragma unroll
    for (int nt = 0; nt < 18; nt++)
#pragma unroll
        for (int r = 0; r < 4; r++) acc[nt][r] = 0.f;

    const uint32_t* qh = g_qpk_hi + (hb * 9 + wm) * 256;
    const uint32_t* ql = g_qpk_lo + (hb * 9 + wm) * 256;
    uint4 qa_h[2], qa_l[2];
#pragma unroll
    for (int ks = 0; ks < 2; ks++) {
        qa_h[ks] = *(const uint4*)&qh[ks * 128 + lane * 4];
        qa_l[ks] = *(const uint4*)&ql[ks * 128 + lane * 4];
    }
    const uint32_t* kh = g_kpk_hi + hb * 2304;
    const uint32_t* kl = g_kpk_lo + hb * 2304;
#pragma unroll
    for (int ks = 0; ks < 2; ks++) {
#pragma unroll
        for (int nt = 0; nt < 18; nt++) {
            uint2 bh = *(const uint2*)&kh[(nt * 2 + ks) * 64 + lane * 2];
            uint2 bl = *(const uint2*)&kl[(nt * 2 + ks) * 64 + lane * 2];
            mma_bf16(acc[nt], (const uint32_t*)&qa_h[ks], (const uint32_t*)&bh);
            mma_bf16(acc[nt], (const uint32_t*)&qa_h[ks], (const uint32_t*)&bl);
            mma_bf16(acc[nt], (const uint32_t*)&qa_l[ks], (const uint32_t*)&bh);
        }
    }

    const int g = lane >> 2, t = lane & 3;
    const int rA = wm * 16 + g, rB = rA + 8;
    {
        uint32_t wA[5], wB[5];
        const uint32_t* mba = g_mbits + (size_t)(w * NT + rA) * 5;
        const uint32_t* mbb = g_mbits + (size_t)(w * NT + rB) * 5;
#pragma unroll
        for (int j = 0; j < 5; j++) { wA[j] = mba[j]; wB[j] = mbb[j]; }

        const float* bb = g_bias + h * NT * NT;
#pragma unroll
        for (int nt = 0; nt < 18; nt++) {
            const int cn = nt * 8 + 2 * t;
            float2 bA = *(const float2*)&bb[rA * NT + cn];
            float2 bB = *(const float2*)&bb[rB * NT + cn];
            const uint32_t bitsA = wA[cn >> 5] >> (cn & 31);
            const uint32_t bitsB = wB[cn >> 5] >> (cn & 31);
            acc[nt][0] = (bitsA & 1u) ? acc[nt][0] + bA.x : -1.0e9f;
            acc[nt][1] = (bitsA & 2u) ? acc[nt][1] + bA.y : -1.0e9f;
            acc[nt][2] = (bitsB & 1u) ? acc[nt][2] + bB.x : -1.0e9f;
            acc[nt][3] = (bitsB & 2u) ? acc[nt][3] + bB.y : -1.0e9f;
        }
        float mxA = -3.0e38f, mxB = -3.0e38f;
#pragma unroll
        for (int nt = 0; nt < 18; nt++) {
            mxA = fmaxf(mxA, fmaxf(acc[nt][0], acc[nt][1]));
            mxB = fmaxf(mxB, fmaxf(acc[nt][2], acc[nt][3]));
        }
#pragma unroll
        for (int o = 1; o <= 2; o <<= 1) {
            mxA = fmaxf(mxA, __shfl_xor_sync(0xffffffffu, mxA, o));
            mxB = fmaxf(mxB, __shfl_xor_sync(0xffffffffu, mxB, o));
        }
        float sA = 0.f, sB = 0.f;
#pragma unroll
        for (int nt = 0; nt < 18; nt++) {
            acc[nt][0] = __expf(acc[nt][0] - mxA); sA += acc[nt][0];
            acc[nt][1] = __expf(acc[nt][1] - mxA); sA += acc[nt][1];
            acc[nt][2] = __expf(acc[nt][2] - mxB); sB += acc[nt][2];
            acc[nt][3] = __expf(acc[nt][3] - mxB); sB += acc[nt][3];
        }
#pragma unroll
        for (int o = 1; o <= 2; o <<= 1) {
            sA += __shfl_xor_sync(0xffffffffu, sA, o);
            sB += __shfl_xor_sync(0xffffffffu, sB, o);
        }
        const float iA = 1.f / sA, iB = 1.f / sB;
#pragma unroll
        for (int nt = 0; nt < 18; nt++) {
            acc[nt][0] *= iA; acc[nt][1] *= iA;
            acc[nt][2] *= iB; acc[nt][3] *= iB;
        }
    }

    __syncthreads();

    float o4[4][4];
#pragma unroll
    for (int nt = 0; nt < 4; nt++)
#pragma unroll
        for (int r = 0; r < 4; r++) o4[nt][r] = 0.f;

#pragma unroll
    for (int kt = 0; kt < 9; kt++) {
        uint32_t ah[4], al[4];
        split2(acc[2 * kt][0],     acc[2 * kt][1],     ah[0], al[0]);
        split2(acc[2 * kt][2],     acc[2 * kt][3],     ah[1], al[1]);
        split2(acc[2 * kt + 1][0], acc[2 * kt + 1][1], ah[2], al[2]);
        split2(acc[2 * kt + 1][2], acc[2 * kt + 1][3], ah[3], al[3]);
#pragma unroll
        for (int nt = 0; nt < 4; nt++) {
            uint2 bh = *(const uint2*)&v_hi[((nt * 9 + kt) * 32 + lane) * 2];
            uint2 bl = *(const uint2*)&v_lo[((nt * 9 + kt) * 32 + lane) * 2];
            mma_bf16(o4[nt], ah, (const uint32_t*)&bh);
            mma_bf16(o4[nt], ah, (const uint32_t*)&bl);
            mma_bf16(o4[nt], al, (const uint32_t*)&bh);
        }
    }

    // ---- write ctx directly as A-fragment bf16-split pack (replaces g_ctx + pack_a<1>) ----
    // Element (row, k=h*32+nt*8+2t): lane matches, reg = rowB + 2*(nt&1), kstep = 2h + (nt>>1).
    {
        const int mtile = w * 9 + wm;
        uint32_t h0, l0, h1, l1, h2, l2, h3, l3;
        split2(o4[0][0], o4[0][1], h0, l0);
        split2(o4[0][2], o4[0][3], h1, l1);
        split2(o4[1][0], o4[1][1], h2, l2);
        split2(o4[1][2], o4[1][3], h3, l3);
        const size_t ib0 = ((size_t)(mtile * KSTEPS + h * 2) * 32 + lane) * 4;
        *(uint4*)&g_cpk_hi[ib0] = make_uint4(h0, h1, h2, h3);
        *(uint4*)&g_cpk_lo[ib0] = make_uint4(l0, l1, l2, l3);
        split2(o4[2][0], o4[2][1], h0, l0);
        split2(o4[2][2], o4[2][3], h1, l1);
        split2(o4[3][0], o4[3][1], h2, l2);
        split2(o4[3][2], o4[3][3], h3, l3);
        const size_t ib1 = ((size_t)(mtile * KSTEPS + h * 2 + 1) * 32 + lane) * 4;
        *(uint4*)&g_cpk_hi[ib1] = make_uint4(h0, h1, h2, h3);
        *(uint4*)&g_cpk_lo[ib1] = make_uint4(l0, l1, l2, l3);
    }
}

// ---------------- launch ----------------
extern "C" void kernel_launch(void* const* d_in, const int* in_sizes, int n_in,
                              void* d_out, int out_size) {
    const float* x     = (const float*)d_in[0];
    const int*   mask  = (const int*)  d_in[1];
    const int*   rel   = (const int*)  d_in[2];
    const float* w_qkv = (const float*)d_in[3];
    const float* b_qkv = (const float*)d_in[4];
    const float* w_out = (const float*)d_in[5];
    const float* b_out = (const float*)d_in[6];
    const float* btab  = (const float*)d_in[7];
    float*       out   = (float*)d_out;

    cudaStream_t stream = cudaStreamLegacy;
    cudaStreamCaptureStatus st = cudaStreamCaptureStatusNone;
    if (cudaStreamIsCapturing(cudaStreamPerThread, &st) == cudaSuccess &&
        st == cudaStreamCaptureStatusActive) {
        stream = cudaStreamPerThread;
    }

    const int GEMM_SMEM = 49152;
    cudaFuncSetAttribute(gemm_mma<0>,
                         cudaFuncAttributeMaxDynamicSharedMemorySize, GEMM_SMEM);
    cudaFuncSetAttribute(gemm_mma<1>,
                         cudaFuncAttributeMaxDynamicSharedMemorySize, GEMM_SMEM);

    prep_kernel<<<(BIAS_ELEMS + 255) / 256, 256, 0, stream>>>(rel, btab, w_qkv, w_out);
    maskbits_kernel<<<(NW * NT * 5 + 255) / 256, 256, 0, stream>>>(mask);
    pack_a_kernel<<<A_PK / 256, 256, 0, stream>>>(x);

    {
        dim3 grid(9, MROWS / 128);
        gemm_mma<0><<<grid, 256, GEMM_SMEM, stream>>>(b_qkv, nullptr);
    }

    attn_kernel<<<NW * NH, 288, 0, stream>>>();

    {
        dim3 grid(3, MROWS / 128);
        gemm_mma<1><<<grid, 256, GEMM_SMEM, stream>>>(b_out, out);
    }
}